// round 5
// baseline (speedup 1.0000x reference)
#include <cuda_runtime.h>
#include <cuda_bf16.h>
#include <cstdint>

// ============================================================================
// DistNet: out[n] = sigmoid((max(min_p ||x_n - p||^2, 0) + alpha)/beta)
//   d2 = ||x||^2 + ||p||^2 - 2 x.p ; min over p commutes with the clip.
// tcgen05 is unavailable (harness PTX targets sm_103 without the 'a' feature
// set), so use legacy mma.sync.m16n8k16 bf16 (tensor pipe, sm_80+ PTX).
//
// Prepass: points f32 -> bf16 rows + ||p||^2 into __device__ globals.
// Main: 256 CTAs x 256 thr (8 warps). Warp owns 32 rows; A fragments (K=128)
// live in 64 regs, loaded once. B (64-point tiles) double-buffered in smem via
// cp.async with XOR swizzle; ldmatrix.x4 -> mma.sync; min epilogue in regs.
// ============================================================================

#define PTOT   2048
#define KDIM   128
#define NTILE  64
#define NTILES (PTOT / NTILE)            // 32
#define WARPS  8
#define CTA_THREADS 256
#define ROWS_PER_WARP 32
#define ROWS_PER_CTA (WARPS * ROWS_PER_WARP)  // 256
#define LOG1000F 6.9077542789816375f

#define BUF_B_BYTES (NTILE * 256)        // 16384: 64 rows x 128 bf16
#define BUF_STRIDE  (BUF_B_BYTES + 256)  // + 64 pn2 floats
#define SM_TOTAL    (2 * BUF_STRIDE)     // 33280 B

// ---------------- device-global scratch (allocation-free) ----------------
__device__ __align__(16) uint4 g_pts_bf16[PTOT * 16];  // [2048][128] bf16
__device__ float g_pn2[PTOT];

// ---------------- small asm helpers ----------------
__device__ __forceinline__ uint32_t smem_u32(const void* p) {
    uint32_t a;
    asm("{ .reg .u64 t; cvta.to.shared.u64 t, %1; cvt.u32.u64 %0, t; }"
        : "=r"(a) : "l"(p));
    return a;
}

__device__ __forceinline__ uint32_t pack_bf16x2(float lo, float hi) {
    uint32_t u;
    asm("cvt.rn.bf16x2.f32 %0, %1, %2;" : "=r"(u) : "f"(hi), "f"(lo));
    return u;
}

__device__ __forceinline__ void cp_async16(uint32_t dst, const void* src) {
    asm volatile("cp.async.cg.shared.global [%0], [%1], 16;"
                 :: "r"(dst), "l"(src) : "memory");
}
__device__ __forceinline__ void cp_commit() {
    asm volatile("cp.async.commit_group;" ::: "memory");
}
__device__ __forceinline__ void cp_wait1() {
    asm volatile("cp.async.wait_group 1;" ::: "memory");
}

__device__ __forceinline__ void ldmatrix_x4(uint32_t& r0, uint32_t& r1,
                                            uint32_t& r2, uint32_t& r3,
                                            uint32_t addr) {
    asm volatile("ldmatrix.sync.aligned.m8n8.x4.shared.b16 {%0,%1,%2,%3}, [%4];"
                 : "=r"(r0), "=r"(r1), "=r"(r2), "=r"(r3) : "r"(addr));
}

__device__ __forceinline__ void mma_16816(float* c, const uint32_t* a,
                                          uint32_t b0, uint32_t b1) {
    asm volatile(
        "mma.sync.aligned.m16n8k16.row.col.f32.bf16.bf16.f32 "
        "{%0,%1,%2,%3}, {%4,%5,%6,%7}, {%8,%9}, {%0,%1,%2,%3};"
        : "+f"(c[0]), "+f"(c[1]), "+f"(c[2]), "+f"(c[3])
        : "r"(a[0]), "r"(a[1]), "r"(a[2]), "r"(a[3]), "r"(b0), "r"(b1));
}

// ---------------- prepass: points f32 -> bf16 + ||p||^2 ----------------
__global__ void prep_points_kernel(const float* __restrict__ pts) {
    int p = blockIdx.x * blockDim.x + threadIdx.x;
    if (p >= PTOT) return;
    const float4* src = reinterpret_cast<const float4*>(pts + (size_t)p * KDIM);
    float s = 0.0f;
#pragma unroll
    for (int i = 0; i < 16; i++) {
        float4 a = src[2 * i];
        float4 b = src[2 * i + 1];
        s += a.x * a.x + a.y * a.y + a.z * a.z + a.w * a.w;
        s += b.x * b.x + b.y * b.y + b.z * b.z + b.w * b.w;
        uint4 o;
        o.x = pack_bf16x2(a.x, a.y);
        o.y = pack_bf16x2(a.z, a.w);
        o.z = pack_bf16x2(b.x, b.y);
        o.w = pack_bf16x2(b.z, b.w);
        g_pts_bf16[p * 16 + i] = o;
    }
    g_pn2[p] = s;
}

// ---------------- main kernel ----------------
__global__ __launch_bounds__(CTA_THREADS, 2) void distnet_kernel(
    const float* __restrict__ x,
    const float* __restrict__ beta_raw,
    float* __restrict__ out)
{
    extern __shared__ char smem[];
    const uint32_t sbase = smem_u32(smem);
    const int tid  = threadIdx.x;
    const int lane = tid & 31;
    const int warp = tid >> 5;
    const int gr   = lane >> 2;        // 0..7: row group within m8
    const int gc   = (lane & 3) * 2;   // 0,2,4,6: col pair

    // ---- double-buffered B-tile loader (B rows swizzled for ldmatrix) ----
    auto issue_tile = [&](int t) {
        const char* srcB = (const char*)g_pts_bf16 + (size_t)t * NTILE * 256;
        uint32_t dbuf = sbase + (uint32_t)(t & 1) * BUF_STRIDE;
#pragma unroll
        for (int i = 0; i < 4; i++) {
            int q = tid + i * CTA_THREADS;       // 0..1023 16B-chunks
            int r = q >> 4, c16 = q & 15;
            uint32_t dst = dbuf + (uint32_t)(r * 256 + ((c16 * 16) ^ ((r & 7) << 4)));
            cp_async16(dst, srcB + q * 16);
        }
        if (tid < 16) {  // 64 pn2 floats = 16 chunks
            cp_async16(dbuf + BUF_B_BYTES + tid * 16,
                       (const char*)g_pn2 + t * NTILE * 4 + tid * 16);
        }
    };

    issue_tile(0); cp_commit();
    issue_tile(1); cp_commit();

    // ---- A prologue: convert 32 rows of x to mma fragments, in registers ----
    // a[mt][kf][0..3]: m16k16 fragment, rows {gr, gr+8}+mt*16, cols kf*16+...
    const int row_base = blockIdx.x * ROWS_PER_CTA + warp * ROWS_PER_WARP;
    uint32_t a[2][8][4];
    float xn2p[4] = {0.f, 0.f, 0.f, 0.f};
#pragma unroll
    for (int mt = 0; mt < 2; mt++) {
        const float* r0p = x + (size_t)(row_base + mt * 16 + gr) * KDIM;
        const float* r1p = r0p + 8 * KDIM;
#pragma unroll
        for (int kf = 0; kf < 8; kf++) {
            int c0 = kf * 16 + gc;
            float2 v00 = *(const float2*)(r0p + c0);
            float2 v10 = *(const float2*)(r1p + c0);
            float2 v01 = *(const float2*)(r0p + c0 + 8);
            float2 v11 = *(const float2*)(r1p + c0 + 8);
            a[mt][kf][0] = pack_bf16x2(v00.x, v00.y);
            a[mt][kf][1] = pack_bf16x2(v10.x, v10.y);
            a[mt][kf][2] = pack_bf16x2(v01.x, v01.y);
            a[mt][kf][3] = pack_bf16x2(v11.x, v11.y);
            xn2p[mt*2]   += v00.x*v00.x + v00.y*v00.y + v01.x*v01.x + v01.y*v01.y;
            xn2p[mt*2+1] += v10.x*v10.x + v10.y*v10.y + v11.x*v11.x + v11.y*v11.y;
        }
    }
    // full ||x||^2 per row: reduce across the 4 lanes sharing a row
#pragma unroll
    for (int j = 0; j < 4; j++) {
        xn2p[j] += __shfl_xor_sync(0xffffffff, xn2p[j], 1);
        xn2p[j] += __shfl_xor_sync(0xffffffff, xn2p[j], 2);
    }

    float mn[4] = {3.4e38f, 3.4e38f, 3.4e38f, 3.4e38f};

    // ---- main loop over 32 tiles of 64 points ----
    for (int t = 0; t < NTILES; t++) {
        cp_wait1();
        __syncthreads();
        const uint32_t buf = sbase + (uint32_t)(t & 1) * BUF_STRIDE;
        const char* pn2s = smem + (t & 1) * BUF_STRIDE + BUF_B_BYTES;

#pragma unroll
        for (int ch = 0; ch < 4; ch++) {   // 16-point chunks
            float acc[4][4] = {{0.f,0.f,0.f,0.f},{0.f,0.f,0.f,0.f},
                               {0.f,0.f,0.f,0.f},{0.f,0.f,0.f,0.f}};
            // ldmatrix.x4 source: matrices (k0-7,n0-7),(k8-15,n0-7),
            //                     (k0-7,n8-15),(k8-15,n8-15)
            const uint32_t nl   = ch * 16 + (lane & 7) + ((lane >> 4) << 3);
            const uint32_t rowb = buf + nl * 256;
            const uint32_t sw   = (nl & 7) << 4;
            const uint32_t halfk = ((lane >> 3) & 1) * 16;
#pragma unroll
            for (int kf = 0; kf < 8; kf++) {
                uint32_t addr = rowb + ((kf * 32 + halfk) ^ sw);
                uint32_t b0, b1, b2, b3;
                ldmatrix_x4(b0, b1, b2, b3, addr);
                mma_16816(acc[0], a[0][kf], b0, b1);
                mma_16816(acc[1], a[0][kf], b2, b3);
                mma_16816(acc[2], a[1][kf], b0, b1);
                mma_16816(acc[3], a[1][kf], b2, b3);
            }
            // epilogue: cand = pn2 - 2*dot, fold into running mins
            float2 p0 = *(const float2*)(pn2s + (ch * 16 + gc) * 4);
            float2 p1 = *(const float2*)(pn2s + (ch * 16 + 8 + gc) * 4);
            mn[0] = fminf(mn[0], fminf(fminf(fmaf(-2.f, acc[0][0], p0.x),
                                             fmaf(-2.f, acc[0][1], p0.y)),
                                       fminf(fmaf(-2.f, acc[1][0], p1.x),
                                             fmaf(-2.f, acc[1][1], p1.y))));
            mn[1] = fminf(mn[1], fminf(fminf(fmaf(-2.f, acc[0][2], p0.x),
                                             fmaf(-2.f, acc[0][3], p0.y)),
                                       fminf(fmaf(-2.f, acc[1][2], p1.x),
                                             fmaf(-2.f, acc[1][3], p1.y))));
            mn[2] = fminf(mn[2], fminf(fminf(fmaf(-2.f, acc[2][0], p0.x),
                                             fmaf(-2.f, acc[2][1], p0.y)),
                                       fminf(fmaf(-2.f, acc[3][0], p1.x),
                                             fmaf(-2.f, acc[3][1], p1.y))));
            mn[3] = fminf(mn[3], fminf(fminf(fmaf(-2.f, acc[2][2], p0.x),
                                             fmaf(-2.f, acc[2][3], p0.y)),
                                       fminf(fmaf(-2.f, acc[3][2], p1.x),
                                             fmaf(-2.f, acc[3][3], p1.y))));
        }
        __syncthreads();
        if (t + 2 < NTILES) issue_tile(t + 2);
        cp_commit();
    }

    // ---- cross-lane min reduce (lanes sharing a row differ in lane&3) ----
#pragma unroll
    for (int j = 0; j < 4; j++) {
        mn[j] = fminf(mn[j], __shfl_xor_sync(0xffffffff, mn[j], 1));
        mn[j] = fminf(mn[j], __shfl_xor_sync(0xffffffff, mn[j], 2));
    }

    // ---- translated sigmoid + store ----
    if ((lane & 3) == 0) {
        float br = __ldg(beta_raw);
        float beta = (br > 15.0f) ? br : log1pf(__expf(br));  // softplus
        float alpha = -beta * LOG1000F;
#pragma unroll
        for (int j = 0; j < 4; j++) {
            float min_d = fmaxf(xn2p[j] + mn[j], 0.0f);
            float z = (min_d + alpha) / beta;
            out[row_base + j * 8 + gr] = 1.0f / (1.0f + __expf(-z));
        }
    }
}

// ---------------- launch ----------------
extern "C" void kernel_launch(void* const* d_in, const int* in_sizes, int n_in,
                              void* d_out, int out_size) {
    const float* x        = (const float*)d_in[0];   // [65536,128]
    const float* points   = (const float*)d_in[1];   // [2048,128]
    const float* beta_raw = (const float*)d_in[2];   // [1]
    float* out = (float*)d_out;                      // [65536]

    prep_points_kernel<<<PTOT / 128, 128>>>(points);

    const int n = in_sizes[0] / KDIM;                // 65536 rows
    distnet_kernel<<<n / ROWS_PER_CTA, CTA_THREADS, SM_TOTAL>>>(x, beta_raw, out);
}